// round 1
// baseline (speedup 1.0000x reference)
#include <cuda_runtime.h>
#include <math.h>

#define B_ROWS 4096
#define N_ROWS 8192
#define D_DIM  256
#define BM 64
#define BN 64
#define BK 64
#define NTHREADS 256
#define NEG_BIG -1.0e30f

// Scratch (device globals; no allocation allowed in kernel_launch)
__device__ float g_znorm[N_ROWS * D_DIM];   // 8 MB, fits in L2
__device__ float g_rowloss[N_ROWS];

// ---------------------------------------------------------------------------
// Kernel 1: L2-normalize rows of z = concat(z_i, z_j). One warp per row.
// ---------------------------------------------------------------------------
__global__ void normalize_kernel(const float* __restrict__ zi,
                                 const float* __restrict__ zj) {
    int warp = (blockIdx.x * blockDim.x + threadIdx.x) >> 5;
    int lane = threadIdx.x & 31;
    if (warp >= N_ROWS) return;
    const float* src = (warp < B_ROWS) ? (zi + (size_t)warp * D_DIM)
                                       : (zj + (size_t)(warp - B_ROWS) * D_DIM);
    const float4* src4 = (const float4*)src;
    float4 v0 = src4[lane];
    float4 v1 = src4[lane + 32];
    float ss = v0.x*v0.x + v0.y*v0.y + v0.z*v0.z + v0.w*v0.w
             + v1.x*v1.x + v1.y*v1.y + v1.z*v1.z + v1.w*v1.w;
    #pragma unroll
    for (int off = 16; off; off >>= 1)
        ss += __shfl_xor_sync(0xffffffffu, ss, off);
    float norm = fmaxf(sqrtf(ss), 1e-12f);
    float inv = 1.0f / norm;
    v0.x *= inv; v0.y *= inv; v0.z *= inv; v0.w *= inv;
    v1.x *= inv; v1.y *= inv; v1.z *= inv; v1.w *= inv;
    float4* dst = (float4*)(g_znorm + (size_t)warp * D_DIM);
    dst[lane]      = v0;
    dst[lane + 32] = v1;
}

// ---------------------------------------------------------------------------
// Kernel 2: tiled GEMM (z_norm @ z_norm^T, scaled by 1/T=2) fused with
// online logsumexp per row + positive-pair capture. Block = 64 i-rows.
// Thread (tx,ty) owns rows {ty+16*ri}, cols {tx+16*ci} of the 64x64 tile
// (strided mapping -> conflict-free smem with stride 65).
// ---------------------------------------------------------------------------
__global__ __launch_bounds__(NTHREADS) void lse_kernel() {
    __shared__ float As[BM * 65];
    __shared__ float Bs[BN * 65];
    __shared__ float m_state[BM];
    __shared__ float s_state[BM];
    __shared__ float pos_state[BM];

    const int tid = threadIdx.x;
    const int tx = tid & 15;
    const int ty = tid >> 4;
    const int rowBase = blockIdx.x * BM;

    if (tid < BM) {
        m_state[tid]   = NEG_BIG;
        s_state[tid]   = 0.0f;
        pos_state[tid] = 0.0f;
    }
    // (first __syncthreads inside the k-loop publishes the init)

    for (int jt = 0; jt < N_ROWS / BN; ++jt) {
        const int j0 = jt * BN;
        float acc[4][4];
        #pragma unroll
        for (int ri = 0; ri < 4; ++ri)
            #pragma unroll
            for (int ci = 0; ci < 4; ++ci) acc[ri][ci] = 0.0f;

        for (int kk = 0; kk < D_DIM; kk += BK) {
            __syncthreads();
            // Load 64x64 chunks of A (i-rows) and B (j-rows), row-major [row][k]
            #pragma unroll
            for (int t = 0; t < 4; ++t) {
                int idx4 = tid + t * NTHREADS;     // 0..1023 float4 slots
                int row  = idx4 >> 4;              // 16 float4 per row
                int c4   = idx4 & 15;
                float4 av = *(const float4*)(g_znorm + (size_t)(rowBase + row) * D_DIM + kk + c4 * 4);
                float4 bv = *(const float4*)(g_znorm + (size_t)(j0 + row) * D_DIM + kk + c4 * 4);
                int sb = row * 65 + c4 * 4;
                As[sb + 0] = av.x; As[sb + 1] = av.y; As[sb + 2] = av.z; As[sb + 3] = av.w;
                Bs[sb + 0] = bv.x; Bs[sb + 1] = bv.y; Bs[sb + 2] = bv.z; Bs[sb + 3] = bv.w;
            }
            __syncthreads();

            #pragma unroll 16
            for (int k = 0; k < BK; ++k) {
                float a[4], b[4];
                #pragma unroll
                for (int q = 0; q < 4; ++q) {
                    a[q] = As[(ty + 16 * q) * 65 + k];
                    b[q] = Bs[(tx + 16 * q) * 65 + k];
                }
                #pragma unroll
                for (int ri = 0; ri < 4; ++ri)
                    #pragma unroll
                    for (int ci = 0; ci < 4; ++ci)
                        acc[ri][ci] = fmaf(a[ri], b[ci], acc[ri][ci]);
            }
        }

        // Fused epilogue: per-row online LSE update + positive capture
        #pragma unroll
        for (int ri = 0; ri < 4; ++ri) {
            const int r  = ty + 16 * ri;
            const int gi = rowBase + r;
            const int posj = (gi < B_ROWS) ? (gi + B_ROWS) : (gi - B_ROWS);
            float v[4];
            float vmax = NEG_BIG;
            #pragma unroll
            for (int ci = 0; ci < 4; ++ci) {
                int gj = j0 + tx + 16 * ci;
                float val = 2.0f * acc[ri][ci];   // /TEMPERATURE (0.5)
                if (gj == gi)   val = NEG_BIG;    // diagonal mask (== ref's -9e15)
                if (gj == posj) pos_state[r] = val;  // unique writer
                v[ci] = val;
                vmax = fmaxf(vmax, val);
            }
            // reduce across the 16 column-threads (half-warp)
            #pragma unroll
            for (int off = 8; off; off >>= 1)
                vmax = fmaxf(vmax, __shfl_xor_sync(0xffffffffu, vmax, off));
            float ssum = 0.0f;
            #pragma unroll
            for (int ci = 0; ci < 4; ++ci)
                ssum += __expf(v[ci] - vmax);     // exp(NEG_BIG - m) == 0
            #pragma unroll
            for (int off = 8; off; off >>= 1)
                ssum += __shfl_xor_sync(0xffffffffu, ssum, off);
            if (tx == 0) {                        // unique owner of row r's state
                float mo = m_state[r];
                float M  = fmaxf(mo, vmax);
                s_state[r] = s_state[r] * __expf(mo - M) + ssum * __expf(vmax - M);
                m_state[r] = M;
            }
        }
    }

    __syncthreads();
    if (tid < BM) {
        // loss_i = LSE_i - sim[i, label_i]
        float loss = m_state[tid] + logf(s_state[tid]) - pos_state[tid];
        g_rowloss[rowBase + tid] = loss;
    }
}

// ---------------------------------------------------------------------------
// Kernel 3: deterministic mean over the 8192 per-row losses.
// ---------------------------------------------------------------------------
__global__ void reduce_kernel(float* __restrict__ out) {
    __shared__ float sbuf[NTHREADS];
    int tid = threadIdx.x;
    float s = 0.0f;
    for (int i = tid; i < N_ROWS; i += NTHREADS) s += g_rowloss[i];
    sbuf[tid] = s;
    __syncthreads();
    #pragma unroll
    for (int off = NTHREADS / 2; off; off >>= 1) {
        if (tid < off) sbuf[tid] += sbuf[tid + off];
        __syncthreads();
    }
    if (tid == 0) out[0] = sbuf[0] / (float)N_ROWS;
}

// ---------------------------------------------------------------------------
extern "C" void kernel_launch(void* const* d_in, const int* in_sizes, int n_in,
                              void* d_out, int out_size) {
    const float* zi = (const float*)d_in[0];
    const float* zj = (const float*)d_in[1];
    float* out = (float*)d_out;

    normalize_kernel<<<(N_ROWS * 32) / NTHREADS, NTHREADS>>>(zi, zj);
    lse_kernel<<<N_ROWS / BM, NTHREADS>>>();
    reduce_kernel<<<1, NTHREADS>>>(out);
}

// round 3
// speedup vs baseline: 27.9466x; 27.9466x over previous
#include <cuda_runtime.h>
#include <cuda_bf16.h>
#include <cstdint>
#include <math.h>

#define B_ROWS 4096
#define N_ROWS 8192
#define D_DIM  256
#define TILE_BYTES 65536     // 128 rows x 256 bf16 (pre-swizzled)
#define SUBK_BYTES 16384     // 128 rows x 64 bf16 sub-tile
#define IDESC_F16 0x8200490u // f32 acc, bf16 a/b, M=128, N=128

// ---- smem layout (dynamic) ----
#define SMEM_A    0
#define SMEM_B0   65536
#define SMEM_B1   131072
#define SMEM_CTRL 196608             // tmem ptr (4B)
#define SMEM_MBAR (SMEM_CTRL + 16)   // 8 barriers x 8B
#define SMEM_SRED (SMEM_CTRL + 128)  // 256 floats
#define SMEM_TOTAL (SMEM_CTRL + 128 + 1024)

// barriers: [0]=b_full0 [1]=b_full1 [2]=b_free0 [3]=b_free1
//           [4]=d_full0 [5]=d_full1 [6]=d_free0 [7]=d_free1
#define BAR(i) (smem_base + SMEM_MBAR + 8 * (i))

// Arch-specific gate: tcgen05 is an 'a'-feature. The harness's extra
// compute_103 (family-portable) gencode pass must see NO tcgen05 PTX.
#if defined(__CUDA_ARCH__) && \
    (defined(__CUDA_ARCH_FEAT_SM103_ALL) || \
     (defined(__CUDA_ARCH_SPECIFIC__) && (__CUDA_ARCH_SPECIFIC__ == 1030)))
#define TC_ENABLED 1
#else
#define TC_ENABLED 0
#endif

// ---- device globals (no allocation allowed) ----
__device__ __align__(16) unsigned char g_zswz[N_ROWS * D_DIM * 2]; // 4MB bf16, pre-swizzled
__device__ float g_ps[2][N_ROWS];
__device__ float g_posd[N_ROWS];

// ---------------- arch-neutral PTX helpers (sm_90 baseline) ----------------
__device__ __forceinline__ uint32_t smem_u32(const void* p) {
    uint32_t a;
    asm("{ .reg .u64 t; cvta.to.shared.u64 t, %1; cvt.u32.u64 %0, t; }" : "=r"(a) : "l"(p));
    return a;
}
#define MBARRIER_INIT(addr, cnt) \
    asm volatile("mbarrier.init.shared.b64 [%0], %1;" :: "r"(addr), "r"((uint32_t)(cnt)) : "memory")
#define MBARRIER_EXPECT_TX(addr, bytes) \
    asm volatile("mbarrier.arrive.expect_tx.shared.b64 _, [%0], %1;" :: "r"(addr), "r"((uint32_t)(bytes)) : "memory")
#define MBARRIER_ARRIVE(addr) \
    asm volatile("mbarrier.arrive.shared.b64 _, [%0];" :: "r"(addr) : "memory")
#define MBARRIER_WAIT_PARITY(addr, par) do {                                   \
    uint32_t _m = (addr), _p = (uint32_t)(par), _done;                          \
    asm volatile("{\n\t.reg .pred p;\n\t"                                       \
        "mbarrier.try_wait.parity.acquire.cta.shared::cta.b64 p, [%1], %2;\n\t" \
        "selp.b32 %0, 1, 0, p;\n\t}" : "=r"(_done) : "r"(_m), "r"(_p) : "memory"); \
    if (!_done) {                                                               \
        asm volatile("{\n\t.reg .pred P1;\n\t"                                  \
            "WL_%=:\n\t"                                                        \
            "mbarrier.try_wait.parity.acquire.cta.shared::cta.b64 P1, [%0], %1, 0x989680;\n\t" \
            "@P1 bra.uni WD_%=;\n\t"                                            \
            "bra.uni WL_%=;\n\t"                                                \
            "WD_%=:\n\t}" :: "r"(_m), "r"(_p) : "memory");                      \
    } } while (0)
#define FENCE_PROXY_ASYNC() asm volatile("fence.proxy.async.shared::cta;" ::: "memory")

__device__ __forceinline__ void bulk_copy(uint32_t dst_smem, const void* src, uint32_t bytes, uint32_t mbar) {
    asm volatile("cp.async.bulk.shared::cluster.global.mbarrier::complete_tx::bytes [%0], [%1], %2, [%3];"
        :: "r"(dst_smem), "l"(src), "r"(bytes), "r"(mbar) : "memory");
}
__device__ __forceinline__ float fast_ex2(float x) {
    float y; asm("ex2.approx.f32 %0, %1;" : "=f"(y) : "f"(x)); return y;
}
__device__ __forceinline__ uint32_t swz128(uint32_t x) { return x ^ ((x >> 3) & 0x70); }

// ---------------- tcgen05 helpers (sm_103a only) ----------------
#if TC_ENABLED
#define TCGEN05_ALLOC(sm, n) \
    asm volatile("tcgen05.alloc.cta_group::1.sync.aligned.shared::cta.b32 [%0], %1;" :: "r"(sm), "r"((uint32_t)(n)) : "memory")
#define TCGEN05_DEALLOC(t, n) \
    asm volatile("tcgen05.dealloc.cta_group::1.sync.aligned.b32 %0, %1;" :: "r"(t), "r"((uint32_t)(n)))
#define TCGEN05_RELINQ() \
    asm volatile("tcgen05.relinquish_alloc_permit.cta_group::1.sync.aligned;")
#define TCGEN05_COMMIT(mb) \
    asm volatile("tcgen05.commit.cta_group::1.mbarrier::arrive::one.shared::cluster.b64 [%0];" :: "r"(mb) : "memory")
#define TCGEN05_WAIT_LD()  asm volatile("tcgen05.wait::ld.sync.aligned;" ::: "memory")
#define TCGEN05_FENCE_BEFORE() asm volatile("tcgen05.fence::before_thread_sync;" ::: "memory")
#define TCGEN05_FENCE_AFTER()  asm volatile("tcgen05.fence::after_thread_sync;" ::: "memory")

#define TCGEN05_LD_X32(r, a) \
    asm volatile("tcgen05.ld.sync.aligned.32x32b.x32.b32 " \
        "{%0,%1,%2,%3,%4,%5,%6,%7,%8,%9,%10,%11,%12,%13,%14,%15," \
        "%16,%17,%18,%19,%20,%21,%22,%23,%24,%25,%26,%27,%28,%29,%30,%31}, [%32];" \
        : "=r"((r)[0]),"=r"((r)[1]),"=r"((r)[2]),"=r"((r)[3]),"=r"((r)[4]),"=r"((r)[5]),"=r"((r)[6]),"=r"((r)[7]), \
          "=r"((r)[8]),"=r"((r)[9]),"=r"((r)[10]),"=r"((r)[11]),"=r"((r)[12]),"=r"((r)[13]),"=r"((r)[14]),"=r"((r)[15]), \
          "=r"((r)[16]),"=r"((r)[17]),"=r"((r)[18]),"=r"((r)[19]),"=r"((r)[20]),"=r"((r)[21]),"=r"((r)[22]),"=r"((r)[23]), \
          "=r"((r)[24]),"=r"((r)[25]),"=r"((r)[26]),"=r"((r)[27]),"=r"((r)[28]),"=r"((r)[29]),"=r"((r)[30]),"=r"((r)[31]) \
        : "r"(a))

// SW128 descriptor: layout=2 (SW128), version=1, SBO=64, LBO=1
__device__ __forceinline__ uint64_t make_desc(uint32_t addr) {
    uint64_t base = (uint64_t(2) << 61) | (uint64_t(1) << 46) | (uint64_t(64) << 32) | (uint64_t(1) << 16);
    return base | ((uint64_t)(addr >> 4) & 0x3FFF);
}
__device__ __forceinline__ void mma_f16_ss(uint32_t d, uint64_t ad, uint64_t bd, uint32_t idesc, bool en) {
    uint32_t e = en ? 1u : 0u;
    asm volatile("{\n\t.reg .pred p;\n\tsetp.ne.u32 p, %5, 0;\n\t"
        "tcgen05.mma.cta_group::1.kind::f16 [%0], %1, %2, %3, {%4,%4,%4,%4}, p;\n\t}"
        :: "r"(d), "l"(ad), "l"(bd), "r"(idesc), "r"(0u), "r"(e) : "memory");
}
#endif // TC_ENABLED

// ---------------------------------------------------------------------------
// Kernel 1: normalize rows, convert to bf16, store PRE-SWIZZLED tile layout.
// Tile t (rows 128t..128t+127): sub-tile kc (K 64-chunk) at t*65536 + kc*16384,
// within: swz128(r*128 + c*2). One warp per row; lane handles 8 consecutive k.
// ---------------------------------------------------------------------------
__global__ void prep_kernel(const float* __restrict__ zi, const float* __restrict__ zj) {
    int warp = (blockIdx.x * blockDim.x + threadIdx.x) >> 5;
    int lane = threadIdx.x & 31;
    if (warp >= N_ROWS) return;
    const float* src = (warp < B_ROWS) ? (zi + (size_t)warp * D_DIM)
                                       : (zj + (size_t)(warp - B_ROWS) * D_DIM);
    const float4* s4 = (const float4*)src;
    float4 v0 = s4[lane * 2];
    float4 v1 = s4[lane * 2 + 1];
    float ss = v0.x*v0.x + v0.y*v0.y + v0.z*v0.z + v0.w*v0.w
             + v1.x*v1.x + v1.y*v1.y + v1.z*v1.z + v1.w*v1.w;
    #pragma unroll
    for (int o = 16; o; o >>= 1) ss += __shfl_xor_sync(0xffffffffu, ss, o);
    float inv = 1.0f / fmaxf(sqrtf(ss), 1e-12f);

    __nv_bfloat162 p0 = __floats2bfloat162_rn(v0.x*inv, v0.y*inv);
    __nv_bfloat162 p1 = __floats2bfloat162_rn(v0.z*inv, v0.w*inv);
    __nv_bfloat162 p2 = __floats2bfloat162_rn(v1.x*inv, v1.y*inv);
    __nv_bfloat162 p3 = __floats2bfloat162_rn(v1.z*inv, v1.w*inv);
    uint4 u;
    u.x = *reinterpret_cast<uint32_t*>(&p0);
    u.y = *reinterpret_cast<uint32_t*>(&p1);
    u.z = *reinterpret_cast<uint32_t*>(&p2);
    u.w = *reinterpret_cast<uint32_t*>(&p3);

    int t = warp >> 7, r = warp & 127;
    int kc = lane >> 3;                         // which K 64-chunk
    uint32_t inner = swz128((uint32_t)(r * 128 + (lane & 7) * 16));
    *reinterpret_cast<uint4*>(g_zswz + (size_t)t * TILE_BYTES + kc * SUBK_BYTES + inner) = u;
}

// ---------------------------------------------------------------------------
// Kernel 2: tcgen05 GEMM (Zn @ Zn^T) fused with fixed-max exp-sum epilogue.
// Grid 128: blockIdx = m (0..63) | h<<6 (j-half). 256 threads (8 warps).
// ---------------------------------------------------------------------------
__global__ __launch_bounds__(256, 1) void gemm_lse_kernel() {
#if TC_ENABLED
    extern __shared__ char smem[];
    const uint32_t smem_base = smem_u32(smem);
    const int tid  = threadIdx.x;
    const int wid  = tid >> 5;
    const int lane = tid & 31;
    const int m    = blockIdx.x & 63;
    const int h    = blockIdx.x >> 6;
    const int jt0  = h * 32;
    const int nt   = 32;
    const int pos_t = m ^ 32;                  // tile holding positive pairs

    // --- setup: TMEM alloc, barriers, resident A tile ---
    if (wid == 0) TCGEN05_ALLOC(smem_base + SMEM_CTRL, 256);
    if (tid == 0) {
        MBARRIER_INIT(BAR(0), 1); MBARRIER_INIT(BAR(1), 1);  // b_full (tx)
        MBARRIER_INIT(BAR(2), 1); MBARRIER_INIT(BAR(3), 1);  // b_free
        MBARRIER_INIT(BAR(4), 1); MBARRIER_INIT(BAR(5), 1);  // d_full
        MBARRIER_INIT(BAR(6), 8); MBARRIER_INIT(BAR(7), 8);  // d_free (8 warps)
    }
    {   // load A tile (pre-swizzled image, plain copy)
        const uint4* src = reinterpret_cast<const uint4*>(g_zswz + (size_t)m * TILE_BYTES);
        uint4* dst = reinterpret_cast<uint4*>(smem + SMEM_A);
        #pragma unroll
        for (int i = 0; i < 16; ++i) dst[tid + i * 256] = src[tid + i * 256];
    }
    __syncthreads();
    uint32_t tmem_base;
    asm volatile("ld.shared.b32 %0, [%1];" : "=r"(tmem_base) : "r"(smem_base + SMEM_CTRL));

    // --- prologue: load B tiles 0,1; issue MMA tile 0 ---
    if (tid == 32) {
        MBARRIER_EXPECT_TX(BAR(0), TILE_BYTES);
        bulk_copy(smem_base + SMEM_B0, g_zswz + (size_t)(jt0 + 0) * TILE_BYTES, TILE_BYTES, BAR(0));
        MBARRIER_EXPECT_TX(BAR(1), TILE_BYTES);
        bulk_copy(smem_base + SMEM_B1, g_zswz + (size_t)(jt0 + 1) * TILE_BYTES, TILE_BYTES, BAR(1));
    }
    if (tid == 0) {
        FENCE_PROXY_ASYNC();                    // A tile STS -> async proxy
        MBARRIER_WAIT_PARITY(BAR(0), 0);
        TCGEN05_FENCE_AFTER();
        #pragma unroll
        for (int kc = 0; kc < 4; ++kc)
            #pragma unroll
            for (int q = 0; q < 4; ++q)
                mma_f16_ss(tmem_base,
                           make_desc(smem_base + SMEM_A)  + kc * 1024 + q * 2,
                           make_desc(smem_base + SMEM_B0) + kc * 1024 + q * 2,
                           IDESC_F16, (kc | q) != 0);
        TCGEN05_COMMIT(BAR(4));
    }

    // --- epilogue state ---
    const int rrow   = (wid & 3) * 32 + lane;          // this thread's row in tile
    const int gi     = m * 128 + rrow;
    const int colbase = (tid >> 7) * 64;               // WG0: cols 0-63, WG1: 64-127
    const float C1 = 2.8853900817779268f;              // 2*log2(e)
    float acc0 = 0.f, acc1 = 0.f, acc2 = 0.f, acc3 = 0.f;

    for (int l = 0; l < nt; ++l) {
        const int s = l & 1, r = l >> 1;
        const int jt_g = jt0 + l;

        // 1. wait D[s] full
        MBARRIER_WAIT_PARITY(BAR(4 + s), r & 1);
        TCGEN05_FENCE_AFTER();

        if (tid == 0) {
            // 2. B buf s consumed by MMA l
            MBARRIER_ARRIVE(BAR(2 + s));
            // 3. issue MMA for tile l+1 into D[s^1]
            if (l + 1 < nt) {
                const int s2 = s ^ 1, r2 = (l + 1) >> 1;
                MBARRIER_WAIT_PARITY(BAR(0 + s2), r2 & 1);
                if (l + 1 >= 2) MBARRIER_WAIT_PARITY(BAR(6 + s2), (r2 - 1) & 1);
                TCGEN05_FENCE_AFTER();
                uint32_t bbuf = smem_base + (s2 ? SMEM_B1 : SMEM_B0);
                #pragma unroll
                for (int kc = 0; kc < 4; ++kc)
                    #pragma unroll
                    for (int q = 0; q < 4; ++q)
                        mma_f16_ss(tmem_base + s2 * 128,
                                   make_desc(smem_base + SMEM_A) + kc * 1024 + q * 2,
                                   make_desc(bbuf)               + kc * 1024 + q * 2,
                                   IDESC_F16, (kc | q) != 0);
                TCGEN05_COMMIT(BAR(4 + s2));
            }
        }
        // 4. producer: load tile l+2 into B[s]
        if (tid == 32 && l + 2 < nt) {
            MBARRIER_WAIT_PARITY(BAR(2 + s), r & 1);
            MBARRIER_EXPECT_TX(BAR(0 + s), TILE_BYTES);
            bulk_copy(smem_base + (s ? SMEM_B1 : SMEM_B0),
                      g_zswz + (size_t)(jt_g + 2) * TILE_BYTES, TILE_BYTES, BAR(0 + s));
        }

        // 5. LDTM this tile's D[s]
        uint32_t dv[64];
        const uint32_t taddr = tmem_base + s * 128 + colbase + ((uint32_t)((tid & 127) >> 5) << 21);
        TCGEN05_LD_X32(dv, taddr);
        TCGEN05_LD_X32(dv + 32, taddr + 32);
        TCGEN05_WAIT_LD();
        TCGEN05_FENCE_BEFORE();
        if (lane == 0) MBARRIER_ARRIVE(BAR(6 + s));

        // 6. exp-sum epilogue (fixed max = 2: e = exp2(2*log2e*(d-1)))
        if (jt_g == m) {                       // diagonal tile: exclude j==i
            #pragma unroll
            for (int c = 0; c < 64; ++c) {
                float d = __uint_as_float(dv[c]);
                float e = fast_ex2(fmaf(d, C1, -C1));
                if (colbase + c == rrow) e = 0.f;
                if ((c & 3) == 0) acc0 += e; else if ((c & 3) == 1) acc1 += e;
                else if ((c & 3) == 2) acc2 += e; else acc3 += e;
            }
        } else if (jt_g == pos_t) {            // positive-pair tile: capture dot
            #pragma unroll
            for (int c = 0; c < 64; ++c) {
                float d = __uint_as_float(dv[c]);
                float e = fast_ex2(fmaf(d, C1, -C1));
                if (colbase + c == rrow) g_posd[gi] = d;
                if ((c & 3) == 0) acc0 += e; else if ((c & 3) == 1) acc1 += e;
                else if ((c & 3) == 2) acc2 += e; else acc3 += e;
            }
        } else {
            #pragma unroll
            for (int c = 0; c < 64; ++c) {
                float d = __uint_as_float(dv[c]);
                float e = fast_ex2(fmaf(d, C1, -C1));
                if ((c & 3) == 0) acc0 += e; else if ((c & 3) == 1) acc1 += e;
                else if ((c & 3) == 2) acc2 += e; else acc3 += e;
            }
        }
    }

    // --- combine the two column-half partials per row, store ---
    float stot = (acc0 + acc1) + (acc2 + acc3);
    float* sred = reinterpret_cast<float*>(smem + SMEM_SRED);
    sred[(tid >> 7) * 128 + rrow] = stot;
    __syncthreads();
    if (tid < 128) g_ps[h][m * 128 + tid] = sred[tid] + sred[128 + tid];

    __syncthreads();
    if (wid == 0) { TCGEN05_RELINQ(); TCGEN05_DEALLOC(tmem_base, 256); }
#endif // TC_ENABLED
}

// ---------------------------------------------------------------------------
// Kernel 3: loss_i = 2 + log(S_i) - 2*d_pos_i ; out = mean.
// ---------------------------------------------------------------------------
__global__ void reduce_kernel(float* __restrict__ out) {
    __shared__ float sbuf[256];
    int tid = threadIdx.x;
    float s = 0.0f;
    for (int i = tid; i < N_ROWS; i += 256) {
        float S = g_ps[0][i] + g_ps[1][i];
        s += 2.0f + logf(S) - 2.0f * g_posd[i];
    }
    sbuf[tid] = s;
    __syncthreads();
    #pragma unroll
    for (int o = 128; o; o >>= 1) {
        if (tid < o) sbuf[tid] += sbuf[tid + o];
        __syncthreads();
    }
    if (tid == 0) out[0] = sbuf[0] / (float)N_ROWS;
}

// ---------------------------------------------------------------------------
extern "C" void kernel_launch(void* const* d_in, const int* in_sizes, int n_in,
                              void* d_out, int out_size) {
    const float* zi = (const float*)d_in[0];
    const float* zj = (const float*)d_in[1];
    float* out = (float*)d_out;

    cudaFuncSetAttribute(gemm_lse_kernel,
                         cudaFuncAttributeMaxDynamicSharedMemorySize, SMEM_TOTAL);

    prep_kernel<<<(N_ROWS * 32) / 256, 256>>>(zi, zj);
    gemm_lse_kernel<<<128, 256, SMEM_TOTAL>>>();
    reduce_kernel<<<1, 256>>>(out);
}